// round 1
// baseline (speedup 1.0000x reference)
#include <cuda_runtime.h>
#include <cuda_bf16.h>
#include <mma.h>

using namespace nvcuda;

// ---------------------------------------------------------------------------
// Problem constants
// ---------------------------------------------------------------------------
#define B_SZ   32
#define C_SZ   256      // C_in == C_out
#define HW     64
#define PIX    4096     // 64*64
#define PODS   2

// 128 MiB scratch: holds F = WHT(x) in (b,c,pix) layout; overwritten in-place
// by the GEMM kernel with S = sum_p softthr(v * W@F).
__device__ float g_scratch[(size_t)B_SZ * C_SZ * PIX];

// ---------------------------------------------------------------------------
// FWHT of 64 elements held as (a = elem[lane], b = elem[lane+32]) per warp.
// Sylvester ordering == np.block([[H,H],[H,-H]]) construction in the reference.
// ---------------------------------------------------------------------------
__device__ __forceinline__ void fwht64(float& a, float& b, int lane) {
    // stride 32 (between the two registers)
    float s = a + b;
    float d = a - b;
    a = s; b = d;
    // strides 16..1 via shuffle butterflies
#pragma unroll
    for (int st = 16; st >= 1; st >>= 1) {
        float ta = __shfl_xor_sync(0xffffffffu, a, st);
        float tb = __shfl_xor_sync(0xffffffffu, b, st);
        a = (lane & st) ? (ta - a) : (a + ta);
        b = (lane & st) ? (tb - b) : (b + tb);
    }
}

// ---------------------------------------------------------------------------
// Kernel 1: forward 2D WHT per (b,c) image. x -> g_scratch (same layout).
// One block (256 thr) per image; smem tile 64x65 (pad kills col-pass conflicts)
// ---------------------------------------------------------------------------
__global__ void __launch_bounds__(256) fwht_fwd_kernel(const float* __restrict__ x) {
    __shared__ float tile[64 * 65];
    const int img = blockIdx.x;                 // b*256 + c
    const float* src = x + (size_t)img * PIX;
    float* dst = g_scratch + (size_t)img * PIX;
    const int t = threadIdx.x;
    const int warp = t >> 5, lane = t & 31;

    // load (coalesced float4)
#pragma unroll
    for (int j = 0; j < 4; j++) {
        int gidx = j * 1024 + t * 4;
        float4 v4 = *reinterpret_cast<const float4*>(src + gidx);
        int r = gidx >> 6, c = gidx & 63;
        float* d = tile + r * 65 + c;
        d[0] = v4.x; d[1] = v4.y; d[2] = v4.z; d[3] = v4.w;
    }
    __syncthreads();

    // row transform (along w): warp handles 8 rows
#pragma unroll
    for (int i = 0; i < 8; i++) {
        int r = warp * 8 + i;
        float a = tile[r * 65 + lane];
        float b = tile[r * 65 + lane + 32];
        fwht64(a, b, lane);
        tile[r * 65 + lane]      = a;
        tile[r * 65 + lane + 32] = b;
    }
    __syncthreads();

    // column transform (along h): warp handles 8 columns
#pragma unroll
    for (int i = 0; i < 8; i++) {
        int c = warp * 8 + i;
        float a = tile[lane * 65 + c];
        float b = tile[(lane + 32) * 65 + c];
        fwht64(a, b, lane);
        tile[lane * 65 + c]        = a;
        tile[(lane + 32) * 65 + c] = b;
    }
    __syncthreads();

    // store
#pragma unroll
    for (int j = 0; j < 4; j++) {
        int gidx = j * 1024 + t * 4;
        int r = gidx >> 6, c = gidx & 63;
        const float* s = tile + r * 65 + c;
        float4 v4 = make_float4(s[0], s[1], s[2], s[3]);
        *reinterpret_cast<float4*>(dst + gidx) = v4;
    }
}

// ---------------------------------------------------------------------------
// Kernel 2: fused dual-pod GEMM + soft-threshold + pod-sum, in-place on scratch
//   For each b: S[b] = sum_p softthr( v[p] * (W[p] @ F[b]), T[p] )
//   M = 256 (o, full), N = 64 pixel tile, K = 256 (c)
//   TF32 wmma (m16n16k8), 8 warps laid out 4(M) x 2(N), warp tile 64x32.
// smem: Bs[256][68] (F panel, K resident) | As[256][36] (W chunk) | Cs[256][64]
// ---------------------------------------------------------------------------
#define NT   64
#define KCH  32
#define LDA  36
#define LDB  68
#define LDC  64
#define GEMM_SMEM_FLOATS (256 * LDB + 256 * LDA + 256 * LDC)
#define GEMM_SMEM_BYTES  (GEMM_SMEM_FLOATS * 4)

__device__ __forceinline__ float softthr(float y, float vv, float tt) {
    float z = vv * y;
    return copysignf(fmaxf(fabsf(z) - tt, 0.0f), z);
}

__global__ void __launch_bounds__(256, 1) gemm_pods_kernel(
    const float* __restrict__ Wg,   // (P, 256, 256)
    const float* __restrict__ vg,   // (P, 4096)
    const float* __restrict__ Tg)   // (P, 4096)
{
    extern __shared__ float sm[];
    float* Bs = sm;                       // 256*68
    float* As = Bs + 256 * LDB;           // 256*36
    float* Cs = As + 256 * LDA;           // 256*64

    const int b    = blockIdx.y;
    const int pix0 = blockIdx.x * NT;
    const int t    = threadIdx.x;
    const int warp = t >> 5;
    const int wm   = warp >> 1;           // 0..3  (M)
    const int wn   = warp & 1;            // 0..1  (N)

    float* Fb = g_scratch + (size_t)b * C_SZ * PIX;

    // ---- load B panel: 256 (c) x 64 (pix), K fully resident ----
#pragma unroll
    for (int i = 0; i < 16; i++) {
        int idx4 = i * 256 + t;           // 4096 float4
        int r  = idx4 >> 4;
        int c4 = (idx4 & 15) * 4;
        float4 v4 = *reinterpret_cast<const float4*>(Fb + (size_t)r * PIX + pix0 + c4);
        *reinterpret_cast<float4*>(Bs + r * LDB + c4) = v4;
    }

    wmma::fragment<wmma::accumulator, 16, 16, 8, float> acc[4][2];

#pragma unroll 1
    for (int p = 0; p < PODS; p++) {
        const float* Wp = Wg + (size_t)p * C_SZ * C_SZ;
#pragma unroll
        for (int mi = 0; mi < 4; mi++)
#pragma unroll
            for (int ni = 0; ni < 2; ni++)
                wmma::fill_fragment(acc[mi][ni], 0.0f);

        for (int kc = 0; kc < C_SZ; kc += KCH) {
            __syncthreads();              // As reuse / (first iter) Bs ready
            // load A chunk: 256 (o) x 32 (c)
#pragma unroll
            for (int i = 0; i < 8; i++) {
                int idx4 = i * 256 + t;   // 2048 float4
                int r  = idx4 >> 3;
                int c4 = (idx4 & 7) * 4;
                float4 w4 = *reinterpret_cast<const float4*>(Wp + (size_t)r * C_SZ + kc + c4);
                *reinterpret_cast<float4*>(As + r * LDA + c4) = w4;
            }
            __syncthreads();

#pragma unroll
            for (int ks = 0; ks < KCH; ks += 8) {
                wmma::fragment<wmma::matrix_a, 16, 16, 8, wmma::precision::tf32, wmma::row_major> af[4];
#pragma unroll
                for (int mi = 0; mi < 4; mi++) {
                    wmma::load_matrix_sync(af[mi], As + (wm * 64 + mi * 16) * LDA + ks, LDA);
#pragma unroll
                    for (int e = 0; e < af[mi].num_elements; e++)
                        af[mi].x[e] = wmma::__float_to_tf32(af[mi].x[e]);
                }
#pragma unroll
                for (int ni = 0; ni < 2; ni++) {
                    wmma::fragment<wmma::matrix_b, 16, 16, 8, wmma::precision::tf32, wmma::row_major> bf;
                    wmma::load_matrix_sync(bf, Bs + (kc + ks) * LDB + wn * 32 + ni * 16, LDB);
#pragma unroll
                    for (int e = 0; e < bf.num_elements; e++)
                        bf.x[e] = wmma::__float_to_tf32(bf.x[e]);
#pragma unroll
                    for (int mi = 0; mi < 4; mi++)
                        wmma::mma_sync(acc[mi][ni], af[mi], bf, acc[mi][ni]);
                }
            }
        }

        if (p == 0) {
            // stage pod-0 into Cs, soft-threshold in place
#pragma unroll
            for (int mi = 0; mi < 4; mi++)
#pragma unroll
                for (int ni = 0; ni < 2; ni++)
                    wmma::store_matrix_sync(Cs + (wm * 64 + mi * 16) * LDC + wn * 32 + ni * 16,
                                            acc[mi][ni], LDC, wmma::mem_row_major);
            __syncthreads();
#pragma unroll
            for (int i = 0; i < 16; i++) {
                int idx4 = i * 256 + t;
                int r  = idx4 >> 4;
                int c4 = (idx4 & 15) * 4;
                int pix = pix0 + c4;
                float4 y = *reinterpret_cast<float4*>(Cs + r * LDC + c4);
                y.x = softthr(y.x, vg[pix + 0], Tg[pix + 0]);
                y.y = softthr(y.y, vg[pix + 1], Tg[pix + 1]);
                y.z = softthr(y.z, vg[pix + 2], Tg[pix + 2]);
                y.w = softthr(y.w, vg[pix + 3], Tg[pix + 3]);
                *reinterpret_cast<float4*>(Cs + r * LDC + c4) = y;
            }
            // next pod's first __syncthreads() orders Cs/As reuse
        } else {
            // B panel is dead after pod-1 K loop: stage pod-1 acc into Bs
            __syncthreads();
#pragma unroll
            for (int mi = 0; mi < 4; mi++)
#pragma unroll
                for (int ni = 0; ni < 2; ni++)
                    wmma::store_matrix_sync(Bs + (wm * 64 + mi * 16) * LDB + wn * 32 + ni * 16,
                                            acc[mi][ni], LDB, wmma::mem_row_major);
            __syncthreads();
            const float* v1 = vg + PIX;
            const float* T1 = Tg + PIX;
#pragma unroll
            for (int i = 0; i < 16; i++) {
                int idx4 = i * 256 + t;
                int r  = idx4 >> 4;
                int c4 = (idx4 & 15) * 4;
                int pix = pix0 + c4;
                float4 y0 = *reinterpret_cast<float4*>(Cs + r * LDC + c4);
                float4 y1 = *reinterpret_cast<float4*>(Bs + r * LDB + c4);
                float4 o;
                o.x = y0.x + softthr(y1.x, v1[pix + 0], T1[pix + 0]);
                o.y = y0.y + softthr(y1.y, v1[pix + 1], T1[pix + 1]);
                o.z = y0.z + softthr(y1.z, v1[pix + 2], T1[pix + 2]);
                o.w = y0.w + softthr(y1.w, v1[pix + 3], T1[pix + 3]);
                *reinterpret_cast<float4*>(Fb + (size_t)r * PIX + pix0 + c4) = o;
            }
        }
    }
}

// ---------------------------------------------------------------------------
// Kernel 3: inverse 2D WHT (scale 1/4096) + residual. scratch -> d_out
// ---------------------------------------------------------------------------
__global__ void __launch_bounds__(256) fwht_inv_kernel(const float* __restrict__ x,
                                                       float* __restrict__ out) {
    __shared__ float tile[64 * 65];
    const int img = blockIdx.x;
    const float* src = g_scratch + (size_t)img * PIX;
    const float* xr  = x + (size_t)img * PIX;
    float* dst = out + (size_t)img * PIX;
    const int t = threadIdx.x;
    const int warp = t >> 5, lane = t & 31;

#pragma unroll
    for (int j = 0; j < 4; j++) {
        int gidx = j * 1024 + t * 4;
        float4 v4 = *reinterpret_cast<const float4*>(src + gidx);
        int r = gidx >> 6, c = gidx & 63;
        float* d = tile + r * 65 + c;
        d[0] = v4.x; d[1] = v4.y; d[2] = v4.z; d[3] = v4.w;
    }
    __syncthreads();

#pragma unroll
    for (int i = 0; i < 8; i++) {
        int r = warp * 8 + i;
        float a = tile[r * 65 + lane];
        float b = tile[r * 65 + lane + 32];
        fwht64(a, b, lane);
        tile[r * 65 + lane]      = a;
        tile[r * 65 + lane + 32] = b;
    }
    __syncthreads();

#pragma unroll
    for (int i = 0; i < 8; i++) {
        int c = warp * 8 + i;
        float a = tile[lane * 65 + c];
        float b = tile[(lane + 32) * 65 + c];
        fwht64(a, b, lane);
        tile[lane * 65 + c]        = a;
        tile[(lane + 32) * 65 + c] = b;
    }
    __syncthreads();

    const float inv = 1.0f / 4096.0f;
#pragma unroll
    for (int j = 0; j < 4; j++) {
        int gidx = j * 1024 + t * 4;
        int r = gidx >> 6, c = gidx & 63;
        const float* s = tile + r * 65 + c;
        float4 xv = *reinterpret_cast<const float4*>(xr + gidx);
        float4 v4;
        v4.x = s[0] * inv + xv.x;
        v4.y = s[1] * inv + xv.y;
        v4.z = s[2] * inv + xv.z;
        v4.w = s[3] * inv + xv.w;
        *reinterpret_cast<float4*>(dst + gidx) = v4;
    }
}

// ---------------------------------------------------------------------------
// Launch
// ---------------------------------------------------------------------------
extern "C" void kernel_launch(void* const* d_in, const int* in_sizes, int n_in,
                              void* d_out, int out_size) {
    const float* x  = (const float*)d_in[0];   // (32, 256, 64, 64)
    const float* v  = (const float*)d_in[1];   // (2, 64, 64)
    const float* W  = (const float*)d_in[2];   // (2, 256, 256)
    const float* T  = (const float*)d_in[3];   // (2, 64, 64)
    float* out = (float*)d_out;

    static bool attr_set = false;
    if (!attr_set) {
        cudaFuncSetAttribute(gemm_pods_kernel,
                             cudaFuncAttributeMaxDynamicSharedMemorySize,
                             GEMM_SMEM_BYTES);
        attr_set = true;
    }

    fwht_fwd_kernel<<<B_SZ * C_SZ, 256>>>(x);
    gemm_pods_kernel<<<dim3(PIX / NT, B_SZ), 256, GEMM_SMEM_BYTES>>>(W, v, T);
    fwht_inv_kernel<<<B_SZ * C_SZ, 256>>>(x, out);
}

// round 3
// speedup vs baseline: 1.1221x; 1.1221x over previous
#include <cuda_runtime.h>
#include <cuda_bf16.h>
#include <cstdint>
#include <mma.h>

using namespace nvcuda;

// ---------------------------------------------------------------------------
// Problem constants
// ---------------------------------------------------------------------------
#define B_SZ   32
#define C_SZ   256      // C_in == C_out
#define PIX    4096     // 64*64
#define PODS   2

// 128 MiB scratch. K1 writes F^T = 2D-WHT(x) in TRANSPOSED pixel order:
// scratch[b][c][w*64+h]. K2 overwrites in place with S (same pixel order).
// K3 un-transposes back while writing d_out.
__device__ float g_scratch[(size_t)B_SZ * C_SZ * PIX];

// ---------------------------------------------------------------------------
// FWHT of 64 elements held as (a = elem[lane], b = elem[lane+32]) per warp.
// ---------------------------------------------------------------------------
__device__ __forceinline__ void fwht64(float& a, float& b, int lane) {
    float s = a + b;
    float d = a - b;
    a = s; b = d;
#pragma unroll
    for (int st = 16; st >= 1; st >>= 1) {
        float ta = __shfl_xor_sync(0xffffffffu, a, st);
        float tb = __shfl_xor_sync(0xffffffffu, b, st);
        a = (lane & st) ? (ta - a) : (a + ta);
        b = (lane & st) ? (tb - b) : (b + tb);
    }
}

// ---------------------------------------------------------------------------
// Kernel 1: forward 2D WHT per (b,c) image; ONE smem transpose round trip.
//   load rows (reg) -> fwht rows -> smem transpose -> fwht cols (reg)
//   -> store TRANSPOSED ([w][h]) coalesced.
// ---------------------------------------------------------------------------
__global__ void __launch_bounds__(256) fwht_fwd_kernel(const float* __restrict__ x) {
    __shared__ float tile[64 * 65];
    const int img = blockIdx.x;                 // b*256 + c
    const float* src = x + (size_t)img * PIX;
    float* dst = g_scratch + (size_t)img * PIX;
    const int t = threadIdx.x;
    const int warp = t >> 5, lane = t & 31;

    float a[8], b[8];
    // row pass (along w, contiguous) fully in registers
#pragma unroll
    for (int i = 0; i < 8; i++) {
        int r = warp * 8 + i;                  // r = h
        a[i] = src[r * 64 + lane];
        b[i] = src[r * 64 + lane + 32];
        fwht64(a[i], b[i], lane);
        // transpose into smem: tile[w][h]
        tile[lane * 65 + r]        = a[i];
        tile[(lane + 32) * 65 + r] = b[i];
    }
    __syncthreads();

    // column pass (along h): read tile rows (= fixed w), conflict-free
#pragma unroll
    for (int i = 0; i < 8; i++) {
        int w = warp * 8 + i;
        float aa = tile[w * 65 + lane];
        float bb = tile[w * 65 + lane + 32];
        fwht64(aa, bb, lane);
        // store transposed layout [w][h]: coalesced
        dst[w * 64 + lane]      = aa;
        dst[w * 64 + lane + 32] = bb;
    }
}

// ---------------------------------------------------------------------------
// Kernel 2: fused dual-pod GEMM + soft-threshold + pod-sum, in-place.
//   Per b: S[b] = sum_p softthr( v[p] * (W[p] @ F[b]), T[p] )
//   M=256 (full o), N=64 pixel tile, K=256. Both pods accumulated in ONE
//   K pass (dual accumulators). A chunks double-buffered via cp.async.
//   TF32 wmma m16n16k8, 8 warps 4(M) x 2(N), warp tile 64x32.
// ---------------------------------------------------------------------------
#define NT   64
#define KCH  32
#define LDA  36
#define LDB  68
#define A_BUF_FLOATS (256 * LDA)                       // 9216 per pod per buffer
#define GEMM_SMEM_FLOATS (256 * LDB + 4 * A_BUF_FLOATS)  // Bs + 2 bufs x 2 pods
#define GEMM_SMEM_BYTES  (GEMM_SMEM_FLOATS * 4)        // 217088 B

__device__ __forceinline__ void cp_async16(float* smem_dst, const float* gsrc) {
    unsigned int s = (unsigned int)__cvta_generic_to_shared(smem_dst);
    asm volatile("cp.async.cg.shared.global [%0], [%1], 16;\n" :: "r"(s), "l"(gsrc));
}
#define CP_COMMIT() asm volatile("cp.async.commit_group;\n" ::: "memory")
#define CP_WAIT0()  asm volatile("cp.async.wait_group 0;\n" ::: "memory")

__device__ __forceinline__ float softthr(float y, float vv, float tt) {
    float z = vv * y;
    return copysignf(fmaxf(fabsf(z) - tt, 0.0f), z);
}

__global__ void __launch_bounds__(256, 1) gemm_pods_kernel(
    const float* __restrict__ Wg,   // (P, 256, 256)
    const float* __restrict__ vg,   // (P, 4096) natural [h][w] order
    const float* __restrict__ Tg)   // (P, 4096)
{
    extern __shared__ float sm[];
    float* Bs = sm;                       // 256*68
    float* As = Bs + 256 * LDB;           // 4 x 9216: [buf][pod]

    const int b    = blockIdx.y;
    const int pix0 = blockIdx.x * NT;
    const int t    = threadIdx.x;
    const int warp = t >> 5;
    const int wm   = warp >> 1;           // 0..3  (M)
    const int wn   = warp & 1;            // 0..1  (N)

    float* Fb = g_scratch + (size_t)b * C_SZ * PIX;
    const float* W0 = Wg;
    const float* W1 = Wg + (size_t)C_SZ * C_SZ;

    // ---- async load B panel: 256 (c) x 64 (pix) ----
#pragma unroll
    for (int i = 0; i < 16; i++) {
        int idx4 = i * 256 + t;           // 4096 float4
        int r  = idx4 >> 4;
        int c4 = (idx4 & 15) * 4;
        cp_async16(Bs + r * LDB + c4, Fb + (size_t)r * PIX + pix0 + c4);
    }
    // ---- prefetch A chunk 0 (both pods) into buffer 0 ----
    {
        float* A0 = As;
        float* A1 = As + A_BUF_FLOATS;
#pragma unroll
        for (int i = 0; i < 8; i++) {
            int idx4 = i * 256 + t;       // 2048 float4 per pod
            int r  = idx4 >> 3;
            int c4 = (idx4 & 7) * 4;
            cp_async16(A0 + r * LDA + c4, W0 + (size_t)r * C_SZ + c4);
            cp_async16(A1 + r * LDA + c4, W1 + (size_t)r * C_SZ + c4);
        }
    }
    CP_COMMIT();

    wmma::fragment<wmma::accumulator, 16, 16, 8, float> acc0[4][2], acc1[4][2];
#pragma unroll
    for (int mi = 0; mi < 4; mi++)
#pragma unroll
        for (int ni = 0; ni < 2; ni++) {
            wmma::fill_fragment(acc0[mi][ni], 0.0f);
            wmma::fill_fragment(acc1[mi][ni], 0.0f);
        }

#pragma unroll 1
    for (int kci = 0; kci < 8; kci++) {
        CP_WAIT0();
        __syncthreads();
        if (kci < 7) {
            // prefetch next chunk into the other buffer (safe: that buffer's
            // readers all passed the sync above)
            int kc = (kci + 1) * KCH;
            float* A0 = As + ((kci + 1) & 1) * 2 * A_BUF_FLOATS;
            float* A1 = A0 + A_BUF_FLOATS;
#pragma unroll
            for (int i = 0; i < 8; i++) {
                int idx4 = i * 256 + t;
                int r  = idx4 >> 3;
                int c4 = (idx4 & 7) * 4;
                cp_async16(A0 + r * LDA + c4, W0 + (size_t)r * C_SZ + kc + c4);
                cp_async16(A1 + r * LDA + c4, W1 + (size_t)r * C_SZ + kc + c4);
            }
            CP_COMMIT();
        }
        // compute on current buffer
        const float* A0 = As + (kci & 1) * 2 * A_BUF_FLOATS;
        const float* A1 = A0 + A_BUF_FLOATS;
#pragma unroll
        for (int ks = 0; ks < KCH; ks += 8) {
            wmma::fragment<wmma::matrix_b, 16, 16, 8, wmma::precision::tf32, wmma::row_major> bf[2];
#pragma unroll
            for (int ni = 0; ni < 2; ni++) {
                wmma::load_matrix_sync(bf[ni], Bs + (kci * KCH + ks) * LDB + wn * 32 + ni * 16, LDB);
#pragma unroll
                for (int e = 0; e < bf[ni].num_elements; e++)
                    bf[ni].x[e] = wmma::__float_to_tf32(bf[ni].x[e]);
            }
#pragma unroll
            for (int mi = 0; mi < 4; mi++) {
                wmma::fragment<wmma::matrix_a, 16, 16, 8, wmma::precision::tf32, wmma::row_major> af0, af1;
                wmma::load_matrix_sync(af0, A0 + (wm * 64 + mi * 16) * LDA + ks, LDA);
                wmma::load_matrix_sync(af1, A1 + (wm * 64 + mi * 16) * LDA + ks, LDA);
#pragma unroll
                for (int e = 0; e < af0.num_elements; e++) {
                    af0.x[e] = wmma::__float_to_tf32(af0.x[e]);
                    af1.x[e] = wmma::__float_to_tf32(af1.x[e]);
                }
#pragma unroll
                for (int ni = 0; ni < 2; ni++) {
                    wmma::mma_sync(acc0[mi][ni], af0, bf[ni], acc0[mi][ni]);
                    wmma::mma_sync(acc1[mi][ni], af1, bf[ni], acc1[mi][ni]);
                }
            }
        }
    }

    // ---- epilogue: stage both pods through (now dead) A-buffer region ----
    float* St0 = As;                   // 256 x 68
    float* St1 = As + 256 * LDB;       // 256 x 68 (fits in 4*9216 floats)
    __syncthreads();
#pragma unroll
    for (int mi = 0; mi < 4; mi++)
#pragma unroll
        for (int ni = 0; ni < 2; ni++) {
            wmma::store_matrix_sync(St0 + (wm * 64 + mi * 16) * LDB + wn * 32 + ni * 16,
                                    acc0[mi][ni], LDB, wmma::mem_row_major);
            wmma::store_matrix_sync(St1 + (wm * 64 + mi * 16) * LDB + wn * 32 + ni * 16,
                                    acc1[mi][ni], LDB, wmma::mem_row_major);
        }
    __syncthreads();

    const float* v0 = vg;          const float* T0 = Tg;
    const float* v1 = vg + PIX;    const float* T1 = Tg + PIX;
#pragma unroll
    for (int i = 0; i < 16; i++) {
        int idx4 = i * 256 + t;
        int r  = idx4 >> 4;
        int c4 = (idx4 & 15) * 4;
        float4 o;
        float* po = &o.x;
#pragma unroll
        for (int j = 0; j < 4; j++) {
            int pix_s = pix0 + c4 + j;                         // scratch order: w*64+h
            int vidx  = ((pix_s & 63) << 6) | (pix_s >> 6);    // natural order: h*64+w
            float y0 = St0[r * LDB + c4 + j];
            float y1 = St1[r * LDB + c4 + j];
            po[j] = softthr(y0, v0[vidx], T0[vidx]) + softthr(y1, v1[vidx], T1[vidx]);
        }
        *reinterpret_cast<float4*>(Fb + (size_t)r * PIX + pix0 + c4) = o;
    }
}

// ---------------------------------------------------------------------------
// Kernel 3: inverse 2D WHT (/4096) + residual; un-transposes scratch order.
// ---------------------------------------------------------------------------
__global__ void __launch_bounds__(256) fwht_inv_kernel(const float* __restrict__ x,
                                                       float* __restrict__ out) {
    __shared__ float tile[64 * 65];
    const int img = blockIdx.x;
    const float* src = g_scratch + (size_t)img * PIX;  // [w][h] order
    const float* xr  = x + (size_t)img * PIX;          // [h][w] order
    float* dst = out + (size_t)img * PIX;              // [h][w] order
    const int t = threadIdx.x;
    const int warp = t >> 5, lane = t & 31;

    float a[8], b[8];
    // first pass: along h (contiguous in scratch layout)
#pragma unroll
    for (int i = 0; i < 8; i++) {
        int w = warp * 8 + i;
        a[i] = src[w * 64 + lane];
        b[i] = src[w * 64 + lane + 32];
        fwht64(a[i], b[i], lane);
        // transpose: tile[h][w]
        tile[lane * 65 + w]        = a[i];
        tile[(lane + 32) * 65 + w] = b[i];
    }
    __syncthreads();

    const float inv = 1.0f / 4096.0f;
    // second pass: along w; finish in natural [h][w] order, coalesced
#pragma unroll
    for (int i = 0; i < 8; i++) {
        int h = warp * 8 + i;
        float aa = tile[h * 65 + lane];
        float bb = tile[h * 65 + lane + 32];
        fwht64(aa, bb, lane);
        dst[h * 64 + lane]      = aa * inv + xr[h * 64 + lane];
        dst[h * 64 + lane + 32] = bb * inv + xr[h * 64 + lane + 32];
    }
}

// ---------------------------------------------------------------------------
// Launch
// ---------------------------------------------------------------------------
extern "C" void kernel_launch(void* const* d_in, const int* in_sizes, int n_in,
                              void* d_out, int out_size) {
    const float* x  = (const float*)d_in[0];   // (32, 256, 64, 64)
    const float* v  = (const float*)d_in[1];   // (2, 64, 64)
    const float* W  = (const float*)d_in[2];   // (2, 256, 256)
    const float* T  = (const float*)d_in[3];   // (2, 64, 64)
    float* out = (float*)d_out;

    static bool attr_set = false;
    if (!attr_set) {
        cudaFuncSetAttribute(gemm_pods_kernel,
                             cudaFuncAttributeMaxDynamicSharedMemorySize,
                             GEMM_SMEM_BYTES);
        attr_set = true;
    }

    fwht_fwd_kernel<<<B_SZ * C_SZ, 256>>>(x);
    gemm_pods_kernel<<<dim3(PIX / NT, B_SZ), 256, GEMM_SMEM_BYTES>>>(W, v, T);
    fwht_inv_kernel<<<B_SZ * C_SZ, 256>>>(x, out);
}